// round 10
// baseline (speedup 1.0000x reference)
#include <cuda_runtime.h>
#include <cuda_fp16.h>
#include <math.h>
#include <stdint.h>

#define TOK 32768
#define CDIM 256
#define MLPD 1024

// ---------------- device scratch ----------------
__device__ __half g_x_h[TOK * CDIM];        // LN1 output (windowed order)
__device__ __half g_y_h[TOK * CDIM];        // LN2 output
__device__ __half g_ctx_h[TOK * CDIM];      // attention context (windowed order)
__device__ __half g_int_h[TOK * MLPD];      // MLP hidden
__device__ __half g_wqkv_h[3 * CDIM * CDIM];
__device__ __half g_wo_h[CDIM * CDIM];
__device__ __half g_w1_h[MLPD * CDIM];
__device__ __half g_w2_h[CDIM * MLPD];
__device__ float g_bqkv[3 * CDIM];
__device__ __half g_qkv[3 * TOK * CDIM];    // [sel][win][head][n][d]
__device__ float g_hidden[TOK * CDIM];

// ---------------- helpers ----------------
__device__ __forceinline__ uint32_t smem_u32(const void* p) {
  uint32_t a;
  asm("{ .reg .u64 t; cvta.to.shared.u64 t, %1; cvt.u32.u64 %0, t; }"
      : "=r"(a) : "l"(p));
  return a;
}

__device__ __forceinline__ void cp16(uint32_t smem, const void* g) {
  asm volatile("cp.async.cg.shared.global [%0], [%1], 16;" :: "r"(smem), "l"(g));
}
#define CP_COMMIT() asm volatile("cp.async.commit_group;" ::: "memory")
#define CP_WAIT2() asm volatile("cp.async.wait_group 2;" ::: "memory")
#define CP_WAIT0() asm volatile("cp.async.wait_group 0;" ::: "memory")

#define LDSM4(r, addr) \
  asm volatile("ldmatrix.sync.aligned.m8n8.x4.shared.b16 {%0,%1,%2,%3}, [%4];" \
               : "=r"((r)[0]), "=r"((r)[1]), "=r"((r)[2]), "=r"((r)[3]) \
               : "r"(addr))

#define LDSM4T(r, addr) \
  asm volatile("ldmatrix.sync.aligned.m8n8.x4.trans.shared.b16 {%0,%1,%2,%3}, [%4];" \
               : "=r"((r)[0]), "=r"((r)[1]), "=r"((r)[2]), "=r"((r)[3]) \
               : "r"(addr))

#define MMA16816(d, a, b0, b1) \
  asm volatile( \
      "mma.sync.aligned.m16n8k16.row.col.f32.f16.f16.f32 " \
      "{%0,%1,%2,%3}, {%4,%5,%6,%7}, {%8,%9}, {%0,%1,%2,%3};" \
      : "+f"((d)[0]), "+f"((d)[1]), "+f"((d)[2]), "+f"((d)[3]) \
      : "r"((a)[0]), "r"((a)[1]), "r"((a)[2]), "r"((a)[3]), \
        "r"(b0), "r"(b1))

// windowed token index -> original token index (+4 cyclic shift)
__device__ __forceinline__ int map_shift(int t) {
  int b = t >> 12, rr = t & 4095;
  int win = rr >> 6, n = rr & 63;
  int wh = win >> 3, ww = win & 7, i = n >> 3, j = n & 7;
  int h = (wh * 8 + i + 4) & 63;
  int w = (ww * 8 + j + 4) & 63;
  return (b << 12) + (h << 6) + w;
}

// ---------------- LayerNorm -> fp16 (one warp per token) -------------------
template <bool GATHER>
__device__ __forceinline__ void ln_body(
    const float* __restrict__ x, const float* __restrict__ gam,
    const float* __restrict__ bet, __half* __restrict__ oh, int blk) {
  int warp = threadIdx.x >> 5, lane = threadIdx.x & 31;
  int t = blk * 8 + warp;
  int src = GATHER ? map_shift(t) : t;
  const float4* xr = (const float4*)(x + (size_t)src * CDIM);
  float4 v0 = xr[lane], v1 = xr[lane + 32];
  float s = v0.x + v0.y + v0.z + v0.w + v1.x + v1.y + v1.z + v1.w;
  float q = v0.x * v0.x + v0.y * v0.y + v0.z * v0.z + v0.w * v0.w +
            v1.x * v1.x + v1.y * v1.y + v1.z * v1.z + v1.w * v1.w;
#pragma unroll
  for (int o = 16; o; o >>= 1) {
    s += __shfl_xor_sync(0xffffffffu, s, o);
    q += __shfl_xor_sync(0xffffffffu, q, o);
  }
  float mean = s * (1.0f / 256.0f);
  float var = q * (1.0f / 256.0f) - mean * mean;
  float rs = rsqrtf(var + 1e-5f);
  const float4* g4 = (const float4*)gam;
  const float4* b4 = (const float4*)bet;
  __half h[4];
  {
    float4 ga = g4[lane], be = b4[lane];
    h[0] = __float2half((v0.x - mean) * rs * ga.x + be.x);
    h[1] = __float2half((v0.y - mean) * rs * ga.y + be.y);
    h[2] = __float2half((v0.z - mean) * rs * ga.z + be.z);
    h[3] = __float2half((v0.w - mean) * rs * ga.w + be.w);
    *(uint2*)(oh + (size_t)t * CDIM + lane * 4) = *(uint2*)h;
  }
  {
    float4 ga = g4[lane + 32], be = b4[lane + 32];
    h[0] = __float2half((v1.x - mean) * rs * ga.x + be.x);
    h[1] = __float2half((v1.y - mean) * rs * ga.y + be.y);
    h[2] = __float2half((v1.z - mean) * rs * ga.z + be.z);
    h[3] = __float2half((v1.w - mean) * rs * ga.w + be.w);
    *(uint2*)(oh + (size_t)t * CDIM + 128 + lane * 4) = *(uint2*)h;
  }
}

__global__ void __launch_bounds__(256) ln2_k(
    const float* __restrict__ x, const float* __restrict__ gam,
    const float* __restrict__ bet, __half* __restrict__ oh) {
  ln_body<false>(x, gam, bet, oh, blockIdx.x);
}

// ---------------- fused: LN1 (blocks 0..4095) + weight prep (4096..4863) ---
__global__ void __launch_bounds__(256) prep_ln1(
    const float* __restrict__ hs, const float* __restrict__ ln1g,
    const float* __restrict__ ln1b,
    const float* __restrict__ wq, const float* __restrict__ wk,
    const float* __restrict__ wv, const float* __restrict__ wo,
    const float* __restrict__ w1, const float* __restrict__ w2,
    const float* __restrict__ bq, const float* __restrict__ bk,
    const float* __restrict__ bv) {
  int b = blockIdx.x;
  if (b < 4096) {
    ln_body<true>(hs, ln1g, ln1b, g_x_h, b);
    return;
  }
  int j = (b - 4096) * 256 + threadIdx.x;  // float4 index, total 196608
  const float* src;
  __half* dst;
  int loc;
  if (j < 16384) { src = wq; dst = g_wqkv_h; loc = j; }
  else if (j < 32768) { src = wk; dst = g_wqkv_h + 65536; loc = j - 16384; }
  else if (j < 49152) { src = wv; dst = g_wqkv_h + 131072; loc = j - 32768; }
  else if (j < 65536) { src = wo; dst = g_wo_h; loc = j - 49152; }
  else if (j < 131072) { src = w1; dst = g_w1_h; loc = j - 65536; }
  else { src = w2; dst = g_w2_h; loc = j - 131072; }
  float4 v = ((const float4*)src)[loc];
  __half h[4];
  h[0] = __float2half(v.x);
  h[1] = __float2half(v.y);
  h[2] = __float2half(v.z);
  h[3] = __float2half(v.w);
  *(uint2*)(dst + loc * 4) = *(uint2*)h;
  if (j < 256) g_bqkv[j] = bq[j];
  else if (j < 512) g_bqkv[j] = bk[j - 256];
  else if (j < 768) g_bqkv[j] = bv[j - 512];
}

// ---------------- HMMA fp16 GEMM: 128x128 CTA, 64x64 warp tile, 4 warps ----
// cp.async 4-stage pipeline, K-slab 32. fp16 epilogues via smem -> STG.128.
template <int EPI>
__global__ void __launch_bounds__(128, 2) gemm_mma(
    const __half* __restrict__ A, const __half* __restrict__ B,
    const float* __restrict__ bias, float* __restrict__ out,
    __half* __restrict__ out_h, const float* __restrict__ extra, int K) {
  extern __shared__ char smraw[];
  const int STG = 20480;
  int tid = threadIdx.x, wid = tid >> 5, lane = tid & 31;
  int warp_row = wid >> 1, warp_col = wid & 1;
  int row0 = blockIdx.y * 128, col0 = blockIdx.x * 128;
  uint32_t sm = smem_u32(smraw);

  float acc[4][8][4];
#pragma unroll
  for (int mi = 0; mi < 4; mi++)
#pragma unroll
    for (int ni = 0; ni < 8; ni++)
#pragma unroll
      for (int u = 0; u < 4; u++) acc[mi][ni][u] = 0.0f;

  int nslabs = K >> 5;
  const __half* Ab = A + (size_t)(row0 + tid) * K;
  const __half* Bb = B + (size_t)(col0 + tid) * K;
  uint32_t soff = tid * 80;

#pragma unroll
  for (int p = 0; p < 3; p++) {
    uint32_t st = sm + p * STG;
    int k0 = p * 32;
#pragma unroll
    for (int c4 = 0; c4 < 4; c4++) {
      cp16(st + soff + c4 * 16, Ab + k0 + c4 * 8);
      cp16(st + 10240 + soff + c4 * 16, Bb + k0 + c4 * 8);
    }
    CP_COMMIT();
  }

  int a_r = warp_row * 64 + (lane & 15);
  int b_r = warp_col * 64 + (lane & 15);
  int oct = lane >> 4;

  for (int s = 0; s < nslabs; s++) {
    CP_WAIT2();
    __syncthreads();
    if (s + 3 < nslabs) {
      uint32_t st = sm + ((s + 3) & 3) * STG;
      int k0 = (s + 3) * 32;
#pragma unroll
      for (int c4 = 0; c4 < 4; c4++) {
        cp16(st + soff + c4 * 16, Ab + k0 + c4 * 8);
        cp16(st + 10240 + soff + c4 * 16, Bb + k0 + c4 * 8);
      }
    }
    CP_COMMIT();

    uint32_t st = sm + (s & 3) * STG;
#pragma unroll
    for (int kk = 0; kk < 2; kk++) {
      uint32_t bh[4][4], ah[4][4];
#pragma unroll
      for (int nb = 0; nb < 4; nb++) {
        uint32_t addr = st + 10240 + (b_r + nb * 16) * 80 + (2 * kk + oct) * 16;
        LDSM4(bh[nb], addr);
      }
#pragma unroll
      for (int mi = 0; mi < 4; mi++) {
        uint32_t addr = st + (a_r + mi * 16) * 80 + (2 * kk + oct) * 16;
        LDSM4(ah[mi], addr);
      }
#pragma unroll
      for (int mi = 0; mi < 4; mi++)
#pragma unroll
        for (int ni = 0; ni < 8; ni++) {
          int nb = ni >> 1, up = ni & 1;
          MMA16816(acc[mi][ni], ah[mi], bh[nb][up], bh[nb][up + 2]);
        }
    }
  }

  // drain async groups; stage buffers reusable for epilogue
  CP_WAIT0();
  __syncthreads();

  int group = lane >> 2, t = lane & 3;

  if (EPI == 0 || EPI == 2) {
    // fp16 outputs: stage 8 rows x 64 cols fp16 per warp, emit STG.128
    float2 bb[8];
#pragma unroll
    for (int ni = 0; ni < 8; ni++)
      bb[ni] = *(const float2*)(bias + col0 + warp_col * 64 + ni * 8 + t * 2);
    uint32_t sbase = sm + wid * 1024;
    char* sbc = smraw + wid * 1024;
#pragma unroll
    for (int mi = 0; mi < 4; mi++) {
#pragma unroll
      for (int half = 0; half < 2; half++) {
#pragma unroll
        for (int ni = 0; ni < 8; ni++) {
          float v0 = acc[mi][ni][2 * half + 0] + bb[ni].x;
          float v1 = acc[mi][ni][2 * half + 1] + bb[ni].y;
          if (EPI == 2) {
            v0 = 0.5f * v0 * (1.0f + erff(v0 * 0.7071067811865476f));
            v1 = 0.5f * v1 * (1.0f + erff(v1 * 0.7071067811865476f));
          }
          __half2 hv = __floats2half2_rn(v0, v1);
          *(__half2*)(sbc + group * 128 + ni * 16 + t * 4) = hv;
        }
        __syncwarp();
#pragma unroll
        for (int pass = 0; pass < 2; pass++) {
          int row = pass * 4 + (lane >> 3);
          int chunk = lane & 7;
          uint4 pkt;
          asm volatile("ld.shared.v4.u32 {%0,%1,%2,%3}, [%4];"
                       : "=r"(pkt.x), "=r"(pkt.y), "=r"(pkt.z), "=r"(pkt.w)
                       : "r"(sbase + row * 128 + chunk * 16));
          int r = row0 + warp_row * 64 + mi * 16 + half * 8 + row;
          int c = col0 + warp_col * 64 + chunk * 8;
          if (EPI == 0) {
            int sel = c >> 8, cw = c & 255;
            int head = cw >> 5, d = cw & 31;
            int win = r >> 6, n = r & 63;
            *(uint4*)(g_qkv + (size_t)sel * (TOK * CDIM) + (size_t)win * 16384 +
                      head * 2048 + n * 32 + d) = pkt;
          } else {
            *(uint4*)(out_h + (size_t)r * MLPD + c) = pkt;
          }
        }
        __syncwarp();
      }
    }
  } else {
#pragma unroll
    for (int mi = 0; mi < 4; mi++) {
#pragma unroll
      for (int half = 0; half < 2; half++) {
        int r = row0 + warp_row * 64 + mi * 16 + group + 8 * half;
        int dst = (EPI == 1) ? map_shift(r) : r;
#pragma unroll
        for (int ni = 0; ni < 8; ni++) {
          int c = col0 + warp_col * 64 + ni * 8 + t * 2;
          size_t off = (size_t)dst * 256 + c;
          float2 bb = *(const float2*)(bias + c);
          float2 ex = *(const float2*)(extra + off);
          float2 v;
          v.x = acc[mi][ni][2 * half + 0] + bb.x + ex.x;
          v.y = acc[mi][ni][2 * half + 1] + bb.y + ex.y;
          *(float2*)(out + off) = v;
        }
      }
    }
  }
}

// ---------------- tensor-core windowed attention --------------------------
__global__ void __launch_bounds__(256) attn_mma(
    const float* __restrict__ rel_table) {
  extern __shared__ char smraw[];
  const int QOFF = 0, KOFF = 20480, VOFF = 40960, ROFF = 61440;
  int tid = threadIdx.x, wid = tid >> 5, lane = tid & 31;
  int win = blockIdx.x >> 1;
  int hgrp = (blockIdx.x & 1) * 4;
  uint32_t smb = smem_u32(smraw);

  size_t gbase = (size_t)win * 16384 + (size_t)hgrp * 2048;
  const __half* qg = g_qkv + gbase;
  const __half* kg = g_qkv + (size_t)TOK * CDIM + gbase;
  const __half* vg = g_qkv + 2 * (size_t)TOK * CDIM + gbase;

#pragma unroll
  for (int p = 0; p < 4; p++) {
    int e = p * 2048 + tid * 8;
    int hl = e >> 11, r = (e >> 5) & 63, ck = (e >> 3) & 3;
    uint32_t so = hl * 5120 + r * 80 + ck * 16;
    *(uint4*)(smraw + QOFF + so) = *(const uint4*)(qg + e);
    *(uint4*)(smraw + KOFF + so) = *(const uint4*)(kg + e);
    *(uint4*)(smraw + VOFF + so) = *(const uint4*)(vg + e);
  }
  for (int i = tid; i < 900; i += 256) {
    int hl = i / 225, idx = i - hl * 225;
    *(float*)(smraw + ROFF + hl * 900 + idx * 4) = rel_table[idx * 8 + hgrp + hl];
  }
  __syncthreads();

  int head_l = wid >> 1;
  int rb = (wid & 1) * 32;
  uint32_t qb = smb + QOFF + head_l * 5120;
  uint32_t kb = smb + KOFF + head_l * 5120;
  uint32_t vb = smb + VOFF + head_l * 5120;
  const float* relh = (const float*)(smraw + ROFF + head_l * 900);

  int g = lane >> 2, t = lane & 3;
  int oct = lane >> 4;

  uint32_t qa[2][2][4];
#pragma unroll
  for (int mi = 0; mi < 2; mi++)
#pragma unroll
    for (int kt = 0; kt < 2; kt++) {
      uint32_t addr = qb + (rb + mi * 16 + (lane & 15)) * 80 +
                      (oct * 8 + kt * 16) * 2;
      LDSM4(qa[mi][kt], addr);
    }

  uint32_t kf[2][8][2];
#pragma unroll
  for (int j = 0; j < 4; j++)
#pragma unroll
    for (int kt = 0; kt < 2; kt++) {
      uint32_t r4[4];
      uint32_t addr = kb + (j * 16 + (lane & 15)) * 80 + (kt * 16 + oct * 8) * 2;
      LDSM4(r4, addr);
      kf[kt][j * 2 + 0][0] = r4[0];
      kf[kt][j * 2 + 0][1] = r4[2];
      kf[kt][j * 2 + 1][0] = r4[1];
      kf[kt][j * 2 + 1][1] = r4[3];
    }

  float sc[2][8][4];
#pragma unroll
  for (int mi = 0; mi < 2; mi++)
#pragma unroll
    for (int nt = 0; nt < 8; nt++) {
#pragma unroll
      for (int u = 0; u < 4; u++) sc[mi][nt][u] = 0.0f;
      MMA16816(sc[mi][nt], qa[mi][0], kf[0][nt][0], kf[0][nt][1]);
      MMA16816(sc[mi][nt], qa[mi][1], kf[1][nt][0], kf[1][nt][1]);
    }

  int nw = win & 63;
  bool eh = (nw >> 3) == 7, ew = (nw & 7) == 7;
  const float scale = 0.17677669529663687f;
  float inv[2][2];
#pragma unroll
  for (int mi = 0; mi < 2; mi++) {
    float rmax[2] = {-1e30f, -1e30f};
#pragma unroll
    for (int h2 = 0; h2 < 2; h2++) {
      int n = rb + mi * 16 + g + 8 * h2;
      int ni_ = n >> 3, nj = n & 7;
      int ridn = (eh ? (ni_ < 4 ? 1 : 2) : 0) * 3 + (ew ? (nj < 4 ? 1 : 2) : 0);
#pragma unroll
      for (int nt = 0; nt < 8; nt++) {
#pragma unroll
        for (int j = 0; j < 2; j++) {
          int m = nt * 8 + 2 * t + j;
          int mi_ = m >> 3, mj = m & 7;
          int ridm = (eh ? (mi_ < 4 ? 1 : 2) : 0) * 3 + (ew ? (mj < 4 ? 1 : 2) : 0);
          float s = sc[mi][nt][2 * h2 + j] * scale +
                    relh[(ni_ - mi_ + 7) * 15 + (nj - mj + 7)];
          if (ridn != ridm) s -= 100.0f;
          sc[mi][nt][2 * h2 + j] = s;
          rmax[h2] = fmaxf(rmax[h2], s);
        }
      }
    }
#pragma unroll
    for (int h2 = 0; h2 < 2; h2++) {
      rmax[h2] = fmaxf(rmax[h2], __shfl_xor_sync(0xffffffffu, rmax[h2], 1));
      rmax[h2] = fmaxf(rmax[h2], __shfl_xor_sync(0xffffffffu, rmax[h2], 2));
    }
    float rsum[2] = {0.0f, 0.0f};
#pragma unroll
    for (int nt = 0; nt < 8; nt++)
#pragma unroll
      for (int u = 0; u < 4; u++) {
        int h2 = u >> 1;
        float e = __expf(sc[mi][nt][u] - rmax[h2]);
        sc[mi][nt][u] = e;
        rsum[h2] += e;
      }
#pragma unroll
    for (int h2 = 0; h2 < 2; h2++) {
      rsum[h2] += __shfl_xor_sync(0xffffffffu, rsum[h2], 1);
      rsum[h2] += __shfl_xor_sync(0xffffffffu, rsum[h2], 2);
      inv[mi][h2] = 1.0f / rsum[h2];
    }
  }

  uint32_t ph[2][4][4];
#pragma unroll
  for (int mi = 0; mi < 2; mi++)
#pragma unroll
    for (int kt = 0; kt < 4; kt++) {
      __half2 a0 = __floats2half2_rn(sc[mi][2 * kt][0], sc[mi][2 * kt][1]);
      __half2 a1 = __floats2half2_rn(sc[mi][2 * kt][2], sc[mi][2 * kt][3]);
      __half2 a2 = __floats2half2_rn(sc[mi][2 * kt + 1][0], sc[mi][2 * kt + 1][1]);
      __half2 a3 = __floats2half2_rn(sc[mi][2 * kt + 1][2], sc[mi][2 * kt + 1][3]);
      ph[mi][kt][0] = *(uint32_t*)&a0;
      ph[mi][kt][1] = *(uint32_t*)&a1;
      ph[mi][kt][2] = *(uint32_t*)&a2;
      ph[mi][kt][3] = *(uint32_t*)&a3;
    }

  uint32_t vf[4][4][2];
#pragma unroll
  for (int kt = 0; kt < 4; kt++)
#pragma unroll
    for (int np = 0; np < 2; np++) {
      uint32_t r4[4];
      uint32_t addr = vb + (kt * 16 + (lane & 15)) * 80 + (np * 16 + oct * 8) * 2;
      LDSM4T(r4, addr);
      vf[kt][np * 2 + 0][0] = r4[0];
      vf[kt][np * 2 + 0][1] = r4[1];
      vf[kt][np * 2 + 1][0] = r4[2];
      vf[kt][np * 2 + 1][1] = r4[3];
    }

  float oc[2][4][4];
#pragma unroll
  for (int mi = 0; mi < 2; mi++)
#pragma unroll
    for (int ni = 0; ni < 4; ni++) {
#pragma unroll
      for (int u = 0; u < 4; u++) oc[mi][ni][u] = 0.0f;
#pragma unroll
      for (int kt = 0; kt < 4; kt++)
        MMA16816(oc[mi][ni], ph[mi][kt], vf[kt][ni][0], vf[kt][ni][1]);
    }

  int head = hgrp + head_l;
#pragma unroll
  for (int mi = 0; mi < 2; mi++)
#pragma unroll
    for (int h2 = 0; h2 < 2; h2++) {
      int n = rb + mi * 16 + g + 8 * h2;
      float iv = inv[mi][h2];
#pragma unroll
      for (int ni = 0; ni < 4; ni++) {
        int d = ni * 8 + 2 * t;
        __half2 hv = __floats2half2_rn(oc[mi][ni][2 * h2 + 0] * iv,
                                       oc[mi][ni][2 * h2 + 1] * iv);
        *(__half2*)(g_ctx_h + ((size_t)win * 64 + n) * 256 + head * 32 + d) = hv;
      }
    }
}

// ---------------- host ----------------
extern "C" void kernel_launch(void* const* d_in, const int* in_sizes, int n_in,
                              void* d_out, int out_size) {
  (void)in_sizes; (void)n_in; (void)out_size;
  const float* hs   = (const float*)d_in[0];
  const float* ln1g = (const float*)d_in[1];
  const float* ln1b = (const float*)d_in[2];
  const float* wq   = (const float*)d_in[3];
  const float* bq   = (const float*)d_in[4];
  const float* wk   = (const float*)d_in[5];
  const float* bk   = (const float*)d_in[6];
  const float* wv   = (const float*)d_in[7];
  const float* bv   = (const float*)d_in[8];
  const float* rel  = (const float*)d_in[9];
  const float* wo   = (const float*)d_in[10];
  const float* bo   = (const float*)d_in[11];
  const float* ln2g = (const float*)d_in[12];
  const float* ln2b = (const float*)d_in[13];
  const float* w1   = (const float*)d_in[14];
  const float* b1   = (const float*)d_in[15];
  const float* w2   = (const float*)d_in[16];
  const float* b2   = (const float*)d_in[17];
  float* out = (float*)d_out;

  __half *xh, *yh, *cxh, *ith, *wqkvh, *woh, *w1h, *w2h;
  float *bqkv, *hid;
  cudaGetSymbolAddress((void**)&xh, g_x_h);
  cudaGetSymbolAddress((void**)&yh, g_y_h);
  cudaGetSymbolAddress((void**)&cxh, g_ctx_h);
  cudaGetSymbolAddress((void**)&ith, g_int_h);
  cudaGetSymbolAddress((void**)&wqkvh, g_wqkv_h);
  cudaGetSymbolAddress((void**)&woh, g_wo_h);
  cudaGetSymbolAddress((void**)&w1h, g_w1_h);
  cudaGetSymbolAddress((void**)&w2h, g_w2_h);
  cudaGetSymbolAddress((void**)&bqkv, g_bqkv);
  cudaGetSymbolAddress((void**)&hid, g_hidden);

  const int SMSZ = 4 * 20480;
  cudaFuncSetAttribute(gemm_mma<0>, cudaFuncAttributeMaxDynamicSharedMemorySize, SMSZ);
  cudaFuncSetAttribute(gemm_mma<1>, cudaFuncAttributeMaxDynamicSharedMemorySize, SMSZ);
  cudaFuncSetAttribute(gemm_mma<2>, cudaFuncAttributeMaxDynamicSharedMemorySize, SMSZ);
  cudaFuncSetAttribute(gemm_mma<3>, cudaFuncAttributeMaxDynamicSharedMemorySize, SMSZ);
  const int ASM = 61440 + 3600;
  cudaFuncSetAttribute(attn_mma, cudaFuncAttributeMaxDynamicSharedMemorySize, ASM);

  prep_ln1<<<4864, 256>>>(hs, ln1g, ln1b, wq, wk, wv, wo, w1, w2, bq, bk, bv);

  gemm_mma<0><<<dim3(6, 256), 128, SMSZ>>>(xh, wqkvh, bqkv, nullptr, nullptr,
                                           nullptr, 256);

  attn_mma<<<1024, 256, ASM>>>(rel);

  gemm_mma<1><<<dim3(2, 256), 128, SMSZ>>>(cxh, woh, bo, hid, nullptr, hs, 256);

  ln2_k<<<4096, 256>>>(hid, ln2g, ln2b, yh);

  gemm_mma<2><<<dim3(8, 256), 128, SMSZ>>>(yh, w1h, b1, nullptr, ith, nullptr, 256);

  gemm_mma<3><<<dim3(2, 256), 128, SMSZ>>>(ith, w2h, b2, out, nullptr, hid, 1024);
}

// round 11
// speedup vs baseline: 1.1369x; 1.1369x over previous
#include <cuda_runtime.h>
#include <cuda_fp16.h>
#include <math.h>
#include <stdint.h>

#define TOK 32768
#define CDIM 256
#define MLPD 1024

// ---------------- device scratch ----------------
__device__ __half g_x_h[TOK * CDIM];        // LN1 output (windowed order)
__device__ __half g_y_h[TOK * CDIM];        // LN2 output
__device__ __half g_ctx_h[TOK * CDIM];      // attention context (windowed order)
__device__ __half g_int_h[TOK * MLPD];      // MLP hidden
__device__ __half g_wqkv_h[3 * CDIM * CDIM];
__device__ __half g_wo_h[CDIM * CDIM];
__device__ __half g_w1_h[MLPD * CDIM];
__device__ __half g_w2_h[CDIM * MLPD];
__device__ float g_bqkv[3 * CDIM];
__device__ __half g_qkv[3 * TOK * CDIM];    // [sel][win][head][n][d]
__device__ float g_hidden[TOK * CDIM];

// ---------------- helpers ----------------
__device__ __forceinline__ uint32_t smem_u32(const void* p) {
  uint32_t a;
  asm("{ .reg .u64 t; cvta.to.shared.u64 t, %1; cvt.u32.u64 %0, t; }"
      : "=r"(a) : "l"(p));
  return a;
}

__device__ __forceinline__ void cp16(uint32_t smem, const void* g) {
  asm volatile("cp.async.cg.shared.global [%0], [%1], 16;" :: "r"(smem), "l"(g));
}
#define CP_COMMIT() asm volatile("cp.async.commit_group;" ::: "memory")
#define CP_WAIT1() asm volatile("cp.async.wait_group 1;" ::: "memory")
#define CP_WAIT0() asm volatile("cp.async.wait_group 0;" ::: "memory")

#define LDSM4(r, addr) \
  asm volatile("ldmatrix.sync.aligned.m8n8.x4.shared.b16 {%0,%1,%2,%3}, [%4];" \
               : "=r"((r)[0]), "=r"((r)[1]), "=r"((r)[2]), "=r"((r)[3]) \
               : "r"(addr))

#define LDSM4T(r, addr) \
  asm volatile("ldmatrix.sync.aligned.m8n8.x4.trans.shared.b16 {%0,%1,%2,%3}, [%4];" \
               : "=r"((r)[0]), "=r"((r)[1]), "=r"((r)[2]), "=r"((r)[3]) \
               : "r"(addr))

#define MMA16816(d, a, b0, b1) \
  asm volatile( \
      "mma.sync.aligned.m16n8k16.row.col.f32.f16.f16.f32 " \
      "{%0,%1,%2,%3}, {%4,%5,%6,%7}, {%8,%9}, {%0,%1,%2,%3};" \
      : "+f"((d)[0]), "+f"((d)[1]), "+f"((d)[2]), "+f"((d)[3]) \
      : "r"((a)[0]), "r"((a)[1]), "r"((a)[2]), "r"((a)[3]), \
        "r"(b0), "r"(b1))

// windowed token index -> original token index (+4 cyclic shift)
__device__ __forceinline__ int map_shift(int t) {
  int b = t >> 12, rr = t & 4095;
  int win = rr >> 6, n = rr & 63;
  int wh = win >> 3, ww = win & 7, i = n >> 3, j = n & 7;
  int h = (wh * 8 + i + 4) & 63;
  int w = (ww * 8 + j + 4) & 63;
  return (b << 12) + (h << 6) + w;
}

// ---------------- LayerNorm -> fp16 (one warp per token) -------------------
template <bool GATHER>
__device__ __forceinline__ void ln_body(
    const float* __restrict__ x, const float* __restrict__ gam,
    const float* __restrict__ bet, __half* __restrict__ oh, int blk) {
  int warp = threadIdx.x >> 5, lane = threadIdx.x & 31;
  int t = blk * 8 + warp;
  int src = GATHER ? map_shift(t) : t;
  const float4* xr = (const float4*)(x + (size_t)src * CDIM);
  float4 v0 = xr[lane], v1 = xr[lane + 32];
  float s = v0.x + v0.y + v0.z + v0.w + v1.x + v1.y + v1.z + v1.w;
  float q = v0.x * v0.x + v0.y * v0.y + v0.z * v0.z + v0.w * v0.w +
            v1.x * v1.x + v1.y * v1.y + v1.z * v1.z + v1.w * v1.w;
#pragma unroll
  for (int o = 16; o; o >>= 1) {
    s += __shfl_xor_sync(0xffffffffu, s, o);
    q += __shfl_xor_sync(0xffffffffu, q, o);
  }
  float mean = s * (1.0f / 256.0f);
  float var = q * (1.0f / 256.0f) - mean * mean;
  float rs = rsqrtf(var + 1e-5f);
  const float4* g4 = (const float4*)gam;
  const float4* b4 = (const float4*)bet;
  __half h[4];
  {
    float4 ga = g4[lane], be = b4[lane];
    h[0] = __float2half((v0.x - mean) * rs * ga.x + be.x);
    h[1] = __float2half((v0.y - mean) * rs * ga.y + be.y);
    h[2] = __float2half((v0.z - mean) * rs * ga.z + be.z);
    h[3] = __float2half((v0.w - mean) * rs * ga.w + be.w);
    *(uint2*)(oh + (size_t)t * CDIM + lane * 4) = *(uint2*)h;
  }
  {
    float4 ga = g4[lane + 32], be = b4[lane + 32];
    h[0] = __float2half((v1.x - mean) * rs * ga.x + be.x);
    h[1] = __float2half((v1.y - mean) * rs * ga.y + be.y);
    h[2] = __float2half((v1.z - mean) * rs * ga.z + be.z);
    h[3] = __float2half((v1.w - mean) * rs * ga.w + be.w);
    *(uint2*)(oh + (size_t)t * CDIM + 128 + lane * 4) = *(uint2*)h;
  }
}

__global__ void __launch_bounds__(256) ln2_k(
    const float* __restrict__ x, const float* __restrict__ gam,
    const float* __restrict__ bet, __half* __restrict__ oh) {
  ln_body<false>(x, gam, bet, oh, blockIdx.x);
}

// ---------------- fused: LN1 (blocks 0..4095) + weight prep (4096..4863) ---
__global__ void __launch_bounds__(256) prep_ln1(
    const float* __restrict__ hs, const float* __restrict__ ln1g,
    const float* __restrict__ ln1b,
    const float* __restrict__ wq, const float* __restrict__ wk,
    const float* __restrict__ wv, const float* __restrict__ wo,
    const float* __restrict__ w1, const float* __restrict__ w2,
    const float* __restrict__ bq, const float* __restrict__ bk,
    const float* __restrict__ bv) {
  int b = blockIdx.x;
  if (b < 4096) {
    ln_body<true>(hs, ln1g, ln1b, g_x_h, b);
    return;
  }
  int j = (b - 4096) * 256 + threadIdx.x;  // float4 index, total 196608
  const float* src;
  __half* dst;
  int loc;
  if (j < 16384) { src = wq; dst = g_wqkv_h; loc = j; }
  else if (j < 32768) { src = wk; dst = g_wqkv_h + 65536; loc = j - 16384; }
  else if (j < 49152) { src = wv; dst = g_wqkv_h + 131072; loc = j - 32768; }
  else if (j < 65536) { src = wo; dst = g_wo_h; loc = j - 49152; }
  else if (j < 131072) { src = w1; dst = g_w1_h; loc = j - 65536; }
  else { src = w2; dst = g_w2_h; loc = j - 131072; }
  float4 v = ((const float4*)src)[loc];
  __half h[4];
  h[0] = __float2half(v.x);
  h[1] = __float2half(v.y);
  h[2] = __float2half(v.z);
  h[3] = __float2half(v.w);
  *(uint2*)(dst + loc * 4) = *(uint2*)h;
  if (j < 256) g_bqkv[j] = bq[j];
  else if (j < 512) g_bqkv[j] = bk[j - 256];
  else if (j < 768) g_bqkv[j] = bv[j - 512];
}

// ---------------- HMMA fp16 GEMM: 128x128 CTA, 64x32 warp tile, 8 warps ----
// K-slab 64, 3-stage cp.async ring (144B row stride, conflict-free ldmatrix).
// fp16 epilogues staged through smem -> STG.128.
template <int EPI>
__global__ void __launch_bounds__(256, 2) gemm_mma(
    const __half* __restrict__ A, const __half* __restrict__ B,
    const float* __restrict__ bias, float* __restrict__ out,
    __half* __restrict__ out_h, const float* __restrict__ extra, int K) {
  extern __shared__ char smraw[];
  const int STG = 36864;  // per stage: A 128*144 + B 128*144
  const int BOFF = 18432;
  int tid = threadIdx.x, wid = tid >> 5, lane = tid & 31;
  int warp_row = wid >> 2, warp_col = wid & 3;
  int row0 = blockIdx.y * 128, col0 = blockIdx.x * 128;
  uint32_t sm = smem_u32(smraw);

  float acc[4][4][4];
#pragma unroll
  for (int mi = 0; mi < 4; mi++)
#pragma unroll
    for (int ni = 0; ni < 4; ni++)
#pragma unroll
      for (int u = 0; u < 4; u++) acc[mi][ni][u] = 0.0f;

  int nslabs = K >> 6;
  int lrow = tid >> 1;           // 0..127
  int lhalf = tid & 1;           // which 64B half of the 128B row
  const __half* Ab = A + (size_t)(row0 + lrow) * K + lhalf * 32;
  const __half* Bb = B + (size_t)(col0 + lrow) * K + lhalf * 32;
  uint32_t soff = lrow * 144 + lhalf * 64;

  // prologue: slabs 0,1 into stages 0,1
#pragma unroll
  for (int p = 0; p < 2; p++) {
    uint32_t st = sm + p * STG;
    int k0 = p * 64;
#pragma unroll
    for (int c4 = 0; c4 < 4; c4++) {
      cp16(st + soff + c4 * 16, Ab + k0 + c4 * 8);
      cp16(st + BOFF + soff + c4 * 16, Bb + k0 + c4 * 8);
    }
    CP_COMMIT();
  }

  int a_r = warp_row * 64 + (lane & 15);
  int b_r = warp_col * 32 + (lane & 15);
  int oct = lane >> 4;

  int rd = 0, wr = 2;
  for (int s = 0; s < nslabs; s++) {
    CP_WAIT1();
    __syncthreads();
    if (s + 2 < nslabs) {
      uint32_t st = sm + wr * STG;
      int k0 = (s + 2) * 64;
#pragma unroll
      for (int c4 = 0; c4 < 4; c4++) {
        cp16(st + soff + c4 * 16, Ab + k0 + c4 * 8);
        cp16(st + BOFF + soff + c4 * 16, Bb + k0 + c4 * 8);
      }
    }
    CP_COMMIT();

    uint32_t st = sm + rd * STG;
#pragma unroll
    for (int kk = 0; kk < 4; kk++) {
      uint32_t bh[2][4], ah[4][4];
#pragma unroll
      for (int nb = 0; nb < 2; nb++) {
        uint32_t addr = st + BOFF + (b_r + nb * 16) * 144 + (2 * kk + oct) * 16;
        LDSM4(bh[nb], addr);
      }
#pragma unroll
      for (int mi = 0; mi < 4; mi++) {
        uint32_t addr = st + (a_r + mi * 16) * 144 + (2 * kk + oct) * 16;
        LDSM4(ah[mi], addr);
      }
#pragma unroll
      for (int mi = 0; mi < 4; mi++)
#pragma unroll
        for (int ni = 0; ni < 4; ni++) {
          int nb = ni >> 1, up = ni & 1;
          MMA16816(acc[mi][ni], ah[mi], bh[nb][up], bh[nb][up + 2]);
        }
    }
    rd = (rd == 2) ? 0 : rd + 1;
    wr = (wr == 2) ? 0 : wr + 1;
  }

  // drain async groups; stage buffers reusable for epilogue
  CP_WAIT0();
  __syncthreads();

  int group = lane >> 2, t = lane & 3;

  if (EPI == 0 || EPI == 2) {
    // fp16 outputs: stage 8x32 fp16 per warp in smem, emit STG.128 (64B/quad)
    float2 bb[4];
#pragma unroll
    for (int ni = 0; ni < 4; ni++)
      bb[ni] = *(const float2*)(bias + col0 + warp_col * 32 + ni * 8 + t * 2);
    uint32_t sbase = sm + wid * 512;
    char* sbc = smraw + wid * 512;
#pragma unroll
    for (int mi = 0; mi < 4; mi++) {
#pragma unroll
      for (int half = 0; half < 2; half++) {
#pragma unroll
        for (int ni = 0; ni < 4; ni++) {
          float v0 = acc[mi][ni][2 * half + 0] + bb[ni].x;
          float v1 = acc[mi][ni][2 * half + 1] + bb[ni].y;
          if (EPI == 2) {
            v0 = 0.5f * v0 * (1.0f + erff(v0 * 0.7071067811865476f));
            v1 = 0.5f * v1 * (1.0f + erff(v1 * 0.7071067811865476f));
          }
          __half2 hv = __floats2half2_rn(v0, v1);
          *(__half2*)(sbc + group * 64 + ni * 16 + t * 4) = hv;
        }
        __syncwarp();
        uint4 pkt;
        asm volatile("ld.shared.v4.u32 {%0,%1,%2,%3}, [%4];"
                     : "=r"(pkt.x), "=r"(pkt.y), "=r"(pkt.z), "=r"(pkt.w)
                     : "r"(sbase + group * 64 + t * 16));
        int r = row0 + warp_row * 64 + mi * 16 + group + 8 * half;
        int c = col0 + warp_col * 32 + t * 8;
        if (EPI == 0) {
          int sel = c >> 8, cw = c & 255;
          int head = cw >> 5, d = cw & 31;
          int win = r >> 6, n = r & 63;
          *(uint4*)(g_qkv + (size_t)sel * (TOK * CDIM) + (size_t)win * 16384 +
                    head * 2048 + n * 32 + d) = pkt;
        } else {
          *(uint4*)(out_h + (size_t)r * MLPD + c) = pkt;
        }
        __syncwarp();
      }
    }
  } else {
#pragma unroll
    for (int mi = 0; mi < 4; mi++) {
#pragma unroll
      for (int half = 0; half < 2; half++) {
        int r = row0 + warp_row * 64 + mi * 16 + group + 8 * half;
        int dst = (EPI == 1) ? map_shift(r) : r;
#pragma unroll
        for (int ni = 0; ni < 4; ni++) {
          int c = col0 + warp_col * 32 + ni * 8 + t * 2;
          size_t off = (size_t)dst * 256 + c;
          float2 bb = *(const float2*)(bias + c);
          float2 ex = *(const float2*)(extra + off);
          float2 v;
          v.x = acc[mi][ni][2 * half + 0] + bb.x + ex.x;
          v.y = acc[mi][ni][2 * half + 1] + bb.y + ex.y;
          *(float2*)(out + off) = v;
        }
      }
    }
  }
}

// ---------------- tensor-core windowed attention --------------------------
__global__ void __launch_bounds__(256) attn_mma(
    const float* __restrict__ rel_table) {
  extern __shared__ char smraw[];
  const int QOFF = 0, KOFF = 20480, VOFF = 40960, ROFF = 61440;
  int tid = threadIdx.x, wid = tid >> 5, lane = tid & 31;
  int win = blockIdx.x >> 1;
  int hgrp = (blockIdx.x & 1) * 4;
  uint32_t smb = smem_u32(smraw);

  size_t gbase = (size_t)win * 16384 + (size_t)hgrp * 2048;
  const __half* qg = g_qkv + gbase;
  const __half* kg = g_qkv + (size_t)TOK * CDIM + gbase;
  const __half* vg = g_qkv + 2 * (size_t)TOK * CDIM + gbase;

#pragma unroll
  for (int p = 0; p < 4; p++) {
    int e = p * 2048 + tid * 8;
    int hl = e >> 11, r = (e >> 5) & 63, ck = (e >> 3) & 3;
    uint32_t so = hl * 5120 + r * 80 + ck * 16;
    *(uint4*)(smraw + QOFF + so) = *(const uint4*)(qg + e);
    *(uint4*)(smraw + KOFF + so) = *(const uint4*)(kg + e);
    *(uint4*)(smraw + VOFF + so) = *(const uint4*)(vg + e);
  }
  for (int i = tid; i < 900; i += 256) {
    int hl = i / 225, idx = i - hl * 225;
    *(float*)(smraw + ROFF + hl * 900 + idx * 4) = rel_table[idx * 8 + hgrp + hl];
  }
  __syncthreads();

  int head_l = wid >> 1;
  int rb = (wid & 1) * 32;
  uint32_t qb = smb + QOFF + head_l * 5120;
  uint32_t kb = smb + KOFF + head_l * 5120;
  uint32_t vb = smb + VOFF + head_l * 5120;
  const float* relh = (const float*)(smraw + ROFF + head_l * 900);

  int g = lane >> 2, t = lane & 3;
  int oct = lane >> 4;

  uint32_t qa[2][2][4];
#pragma unroll
  for (int mi = 0; mi < 2; mi++)
#pragma unroll
    for (int kt = 0; kt < 2; kt++) {
      uint32_t addr = qb + (rb + mi * 16 + (lane & 15)) * 80 +
                      (oct * 8 + kt * 16) * 2;
      LDSM4(qa[mi][kt], addr);
    }

  uint32_t kf[2][8][2];
#pragma unroll
  for (int j = 0; j < 4; j++)
#pragma unroll
    for (int kt = 0; kt < 2; kt++) {
      uint32_t r4[4];
      uint32_t addr = kb + (j * 16 + (lane & 15)) * 80 + (kt * 16 + oct * 8) * 2;
      LDSM4(r4, addr);
      kf[kt][j * 2 + 0][0] = r4[0];
      kf[kt][j * 2 + 0][1] = r4[2];
      kf[kt][j * 2 + 1][0] = r4[1];
      kf[kt][j * 2 + 1][1] = r4[3];
    }

  float sc[2][8][4];
#pragma unroll
  for (int mi = 0; mi < 2; mi++)
#pragma unroll
    for (int nt = 0; nt < 8; nt++) {
#pragma unroll
      for (int u = 0; u < 4; u++) sc[mi][nt][u] = 0.0f;
      MMA16816(sc[mi][nt], qa[mi][0], kf[0][nt][0], kf[0][nt][1]);
      MMA16816(sc[mi][nt], qa[mi][1], kf[1][nt][0], kf[1][nt][1]);
    }

  int nw = win & 63;
  bool eh = (nw >> 3) == 7, ew = (nw & 7) == 7;
  const float scale = 0.17677669529663687f;
  float inv[2][2];
#pragma unroll
  for (int mi = 0; mi < 2; mi++) {
    float rmax[2] = {-1e30f, -1e30f};
#pragma unroll
    for (int h2 = 0; h2 < 2; h2++) {
      int n = rb + mi * 16 + g + 8 * h2;
      int ni_ = n >> 3, nj = n & 7;
      int ridn = (eh ? (ni_ < 4 ? 1 : 2) : 0) * 3 + (ew ? (nj < 4 ? 1 : 2) : 0);
#pragma unroll
      for (int nt = 0; nt < 8; nt++) {
#pragma unroll
        for (int j = 0; j < 2; j++) {
          int m = nt * 8 + 2 * t + j;
          int mi_ = m >> 3, mj = m & 7;
          int ridm = (eh ? (mi_ < 4 ? 1 : 2) : 0) * 3 + (ew ? (mj < 4 ? 1 : 2) : 0);
          float s = sc[mi][nt][2 * h2 + j] * scale +
                    relh[(ni_ - mi_ + 7) * 15 + (nj - mj + 7)];
          if (ridn != ridm) s -= 100.0f;
          sc[mi][nt][2 * h2 + j] = s;
          rmax[h2] = fmaxf(rmax[h2], s);
        }
      }
    }
#pragma unroll
    for (int h2 = 0; h2 < 2; h2++) {
      rmax[h2] = fmaxf(rmax[h2], __shfl_xor_sync(0xffffffffu, rmax[h2], 1));
      rmax[h2] = fmaxf(rmax[h2], __shfl_xor_sync(0xffffffffu, rmax[h2], 2));
    }
    float rsum[2] = {0.0f, 0.0f};
#pragma unroll
    for (int nt = 0; nt < 8; nt++)
#pragma unroll
      for (int u = 0; u < 4; u++) {
        int h2 = u >> 1;
        float e = __expf(sc[mi][nt][u] - rmax[h2]);
        sc[mi][nt][u] = e;
        rsum[h2] += e;
      }
#pragma unroll
    for (int h2 = 0; h2 < 2; h2++) {
      rsum[h2] += __shfl_xor_sync(0xffffffffu, rsum[h2], 1);
      rsum[h2] += __shfl_xor_sync(0xffffffffu, rsum[h2], 2);
      inv[mi][h2] = 1.0f / rsum[h2];
    }
  }

  uint32_t ph[2][4][4];
#pragma unroll
  for (int mi = 0; mi < 2; mi++)
#pragma unroll
    for (int kt = 0; kt < 4; kt++) {
      __half2 a0 = __floats2half2_rn(sc[mi][2 * kt][0], sc[mi][2 * kt][1]);
      __half2 a1 = __floats2half2_rn(sc[mi][2 * kt][2], sc[mi][2 * kt][3]);
      __half2 a2 = __floats2half2_rn(sc[mi][2 * kt + 1][0], sc[mi][2 * kt + 1][1]);
      __half2 a3 = __floats2half2_rn(sc[mi][2 * kt + 1][2], sc[mi][2 * kt + 1][3]);
      ph[mi][kt][0] = *(uint32_t*)&a0;
      ph[mi][kt][1] = *(uint32_t*)&a1;
      ph[mi][kt][2] = *(uint32_t*)&a2;
      ph[mi][kt][3] = *(uint32_t*)&a3;
    }

  uint32_t vf[4][4][2];
#pragma unroll
  for (int kt = 0; kt < 4; kt++)
#pragma unroll
    for (int np = 0; np < 2; np++) {
      uint32_t r4[4];
      uint32_t addr = vb + (kt * 16 + (lane & 15)) * 80 + (np * 16 + oct * 8) * 2;
      LDSM4T(r4, addr);
      vf[kt][np * 2 + 0][0] = r4[0];
      vf[kt][np * 2 + 0][1] = r4[1];
      vf[kt][np * 2 + 1][0] = r4[2];
      vf[kt][np * 2 + 1][1] = r4[3];
    }

  float oc[2][4][4];
#pragma unroll
  for (int mi = 0; mi < 2; mi++)
#pragma unroll
    for (int ni = 0; ni < 4; ni++) {
#pragma unroll
      for (int u = 0; u < 4; u++) oc[mi][ni][u] = 0.0f;
#pragma unroll
      for (int kt = 0; kt < 4; kt++)
        MMA16816(oc[mi][ni], ph[mi][kt], vf[kt][ni][0], vf[kt][ni][1]);
    }

  int head = hgrp + head_l;
#pragma unroll
  for (int mi = 0; mi < 2; mi++)
#pragma unroll
    for (int h2 = 0; h2 < 2; h2++) {
      int n = rb + mi * 16 + g + 8 * h2;
      float iv = inv[mi][h2];
#pragma unroll
      for (int ni = 0; ni < 4; ni++) {
        int d = ni * 8 + 2 * t;
        __half2 hv = __floats2half2_rn(oc[mi][ni][2 * h2 + 0] * iv,
                                       oc[mi][ni][2 * h2 + 1] * iv);
        *(__half2*)(g_ctx_h + ((size_t)win * 64 + n) * 256 + head * 32 + d) = hv;
      }
    }
}

// ---------------- host ----------------
extern "C" void kernel_launch(void* const* d_in, const int* in_sizes, int n_in,
                              void* d_out, int out_size) {
  (void)in_sizes; (void)n_in; (void)out_size;
  const float* hs   = (const float*)d_in[0];
  const float* ln1g = (const float*)d_in[1];
  const float* ln1b = (const float*)d_in[2];
  const float* wq   = (const float*)d_in[3];
  const float* bq   = (const float*)d_in[4];
  const float* wk   = (const float*)d_in[5];
  const float* bk   = (const float*)d_in[6];
  const float* wv   = (const float*)d_in[7];
  const float* bv   = (const float*)d_in[8];
  const float* rel  = (const float*)d_in[9];
  const float* wo   = (const float*)d_in[10];
  const float* bo   = (const float*)d_in[11];
  const float* ln2g = (const float*)d_in[12];
  const float* ln2b = (const float*)d_in[13];
  const float* w1   = (const float*)d_in[14];
  const float* b1   = (const float*)d_in[15];
  const float* w2   = (const float*)d_in[16];
  const float* b2   = (const float*)d_in[17];
  float* out = (float*)d_out;

  __half *xh, *yh, *cxh, *ith, *wqkvh, *woh, *w1h, *w2h;
  float *bqkv, *hid;
  cudaGetSymbolAddress((void**)&xh, g_x_h);
  cudaGetSymbolAddress((void**)&yh, g_y_h);
  cudaGetSymbolAddress((void**)&cxh, g_ctx_h);
  cudaGetSymbolAddress((void**)&ith, g_int_h);
  cudaGetSymbolAddress((void**)&wqkvh, g_wqkv_h);
  cudaGetSymbolAddress((void**)&woh, g_wo_h);
  cudaGetSymbolAddress((void**)&w1h, g_w1_h);
  cudaGetSymbolAddress((void**)&w2h, g_w2_h);
  cudaGetSymbolAddress((void**)&bqkv, g_bqkv);
  cudaGetSymbolAddress((void**)&hid, g_hidden);

  const int SMSZ = 3 * 36864;  // 3-stage ring, 110592 B
  cudaFuncSetAttribute(gemm_mma<0>, cudaFuncAttributeMaxDynamicSharedMemorySize, SMSZ);
  cudaFuncSetAttribute(gemm_mma<1>, cudaFuncAttributeMaxDynamicSharedMemorySize, SMSZ);
  cudaFuncSetAttribute(gemm_mma<2>, cudaFuncAttributeMaxDynamicSharedMemorySize, SMSZ);
  cudaFuncSetAttribute(gemm_mma<3>, cudaFuncAttributeMaxDynamicSharedMemorySize, SMSZ);
  const int ASM = 61440 + 3600;
  cudaFuncSetAttribute(attn_mma, cudaFuncAttributeMaxDynamicSharedMemorySize, ASM);

  prep_ln1<<<4864, 256>>>(hs, ln1g, ln1b, wq, wk, wv, wo, w1, w2, bq, bk, bv);

  gemm_mma<0><<<dim3(6, 256), 256, SMSZ>>>(xh, wqkvh, bqkv, nullptr, nullptr,
                                           nullptr, 256);

  attn_mma<<<1024, 256, ASM>>>(rel);

  gemm_mma<1><<<dim3(2, 256), 256, SMSZ>>>(cxh, woh, bo, hid, nullptr, hs, 256);

  ln2_k<<<4096, 256>>>(hid, ln2g, ln2b, yh);

  gemm_mma<2><<<dim3(8, 256), 256, SMSZ>>>(yh, w1h, b1, nullptr, ith, nullptr, 256);

  gemm_mma<3><<<dim3(2, 256), 256, SMSZ>>>(ith, w2h, b2, out, nullptr, hid, 1024);
}